// round 7
// baseline (speedup 1.0000x reference)
#include <cuda_runtime.h>
#include <cstdint>

#define DINL __device__ __forceinline__

namespace i8g {

constexpr int SD = 8192, KD = 4096, ND = 4096;
constexpr int BM = 128, BN = 128, BK = 128;     // CTA tile; BK in int8 elements
constexpr int STAGES = 3;
constexpr int NCHUNK = KD / BK;                 // 32
constexpr int THREADS = 256;                    // 8 warps: 2 (M) x 4 (N)

constexpr int A_STAGE = BM * BK;                // 16 KB
constexpr int B_STAGE = BN * BK;                // 16 KB
constexpr uint32_t OFF_A = 0;
constexpr uint32_t OFF_B = STAGES * A_STAGE;    // 48 KB
constexpr uint32_t SMEM_BYTES = OFF_B + STAGES * B_STAGE + 1024;  // ~97 KB

// int8 scratch for decoded inputs (promotion-corrected)
__device__ __align__(16) int8_t g_xq[(size_t)SD * KD];   // 32 MB
__device__ __align__(16) int8_t g_wq[(size_t)ND * KD];   // 16 MB

DINL uint32_t smem_u32(const void* p) {
  uint32_t a;
  asm("{ .reg .u64 t; cvta.to.shared.u64 t, %1; cvt.u32.u64 %0, t; }" : "=r"(a) : "l"(p));
  return a;
}
DINL uint32_t swz(uint32_t o) { return o ^ ((o >> 3) & 0x70); }   // SW128
DINL void cp16(uint32_t d, const void* s) {
  asm volatile("cp.async.cg.shared.global [%0], [%1], 16;" :: "r"(d), "l"(s) : "memory");
}
DINL void cp_commit() { asm volatile("cp.async.commit_group;" ::: "memory"); }
DINL void cp_wait1()  { asm volatile("cp.async.wait_group 1;" ::: "memory"); }

DINL void ldm4(uint32_t* r, uint32_t addr) {
  asm volatile("ldmatrix.sync.aligned.m8n8.x4.shared.b16 {%0,%1,%2,%3}, [%4];"
               : "=r"(r[0]), "=r"(r[1]), "=r"(r[2]), "=r"(r[3]) : "r"(addr) : "memory");
}
DINL void mma_s8(int* d, const uint32_t* a, const uint32_t* b) {
  asm volatile(
      "mma.sync.aligned.m16n8k32.row.col.s32.s8.s8.s32 "
      "{%0,%1,%2,%3}, {%4,%5,%6,%7}, {%8,%9}, {%0,%1,%2,%3};"
      : "+r"(d[0]), "+r"(d[1]), "+r"(d[2]), "+r"(d[3])
      : "r"(a[0]), "r"(a[1]), "r"(a[2]), "r"(a[3]), "r"(b[0]), "r"(b[1]));
}

// ---- input decode: word is either int32 in [-128,127] or float32 of a small int ----
DINL int cvt_word(uint32_t u) {
  const int iv = (int)u;
  if (iv >= -128 && iv <= 127) return iv;          // int32-promoted input
  return __float2int_rn(__uint_as_float(u));       // float32-promoted input
}
DINL uint32_t pack4(uint4 v) {
  const int a = cvt_word(v.x), b = cvt_word(v.y), c = cvt_word(v.z), d = cvt_word(v.w);
  return (uint32_t)(a & 0xff) | ((uint32_t)(b & 0xff) << 8) |
         ((uint32_t)(c & 0xff) << 16) | ((uint32_t)(d & 0xff) << 24);
}

__global__ void __launch_bounds__(256)
pack_kernel(const uint4* __restrict__ src, int which, int n16)
{
  const int idx = blockIdx.x * blockDim.x + threadIdx.x;
  if (idx >= n16) return;
  const uint4* s = src + (size_t)idx * 4;           // 16 source words
  uint4 o;
  o.x = pack4(s[0]); o.y = pack4(s[1]); o.z = pack4(s[2]); o.w = pack4(s[3]);
  uint4* dst = (uint4*)(which ? g_wq : g_xq);
  dst[idx] = o;
}

__global__ void __launch_bounds__(THREADS, 1)
i8gemm_kernel(const float* __restrict__ sxp, const float* __restrict__ swp,
              const float* __restrict__ syp, float* __restrict__ out)
{
  extern __shared__ char smraw[];
  const uint32_t sraw = smem_u32(smraw);
  const uint32_t base = (sraw + 1023u) & ~1023u;   // 1024-align for SW128 math

  const int tid    = threadIdx.x;
  const int wid    = tid >> 5;
  const int lane   = tid & 31;
  const int warp_m = wid & 1;       // 0..1 -> 64-row slab
  const int warp_n = wid >> 1;      // 0..3 -> 32-col slab
  const int m0 = blockIdx.y * BM;
  const int n0 = blockIdx.x * BN;

  const uint32_t abase = base + OFF_A;
  const uint32_t bbase = base + OFF_B;
  const int8_t* __restrict__ x = g_xq;
  const int8_t* __restrict__ w = g_wq;

  // ---- producer: one 128B K-chunk of A[128 rows] + B[128 rows], SW128 swizzled ----
  auto load_chunk = [&](int kc, int st) {
    const int8_t* ga = x + (size_t)m0 * KD + (size_t)kc * BK;
    const uint32_t sa = abase + st * A_STAGE;
    #pragma unroll
    for (int i = 0; i < (BM * BK / 16) / THREADS; i++) {   // 4
      int u = i * THREADS + tid;
      int r = u >> 3, c = (u & 7) << 4;
      cp16(sa + swz((uint32_t)((r << 7) + c)), ga + (size_t)r * KD + c);
    }
    const int8_t* gb = w + (size_t)n0 * KD + (size_t)kc * BK;
    const uint32_t sb = bbase + st * B_STAGE;
    #pragma unroll
    for (int i = 0; i < (BN * BK / 16) / THREADS; i++) {   // 4
      int u = i * THREADS + tid;
      int r = u >> 3, c = (u & 7) << 4;
      cp16(sb + swz((uint32_t)((r << 7) + c)), gb + (size_t)r * KD + c);
    }
  };

  // ---- prologue ----
  #pragma unroll
  for (int s = 0; s < STAGES - 1; s++) { load_chunk(s, s); cp_commit(); }

  // ---- accumulators: warp tile 64x32 => 4x4 m16n8 tiles ----
  int acc[4][4][4];
  #pragma unroll
  for (int i = 0; i < 4; i++)
    #pragma unroll
    for (int j = 0; j < 4; j++)
      #pragma unroll
      for (int k = 0; k < 4; k++) acc[i][j][k] = 0;

  // ldmatrix per-lane address components
  const uint32_t a_row_l = (uint32_t)(warp_m * 64 + (lane & 15));
  const uint32_t a_byt_l = (uint32_t)((lane >> 4) << 4);
  const uint32_t b_row_l = (uint32_t)(warp_n * 32 + (lane & 7) + ((lane & 16) ? 8 : 0));
  const uint32_t b_byt_l = (uint32_t)((lane & 8) ? 16 : 0);

  // ---- mainloop ----
  for (int kc = 0; kc < NCHUNK; kc++) {
    const int st = kc % STAGES;
    cp_wait1();            // chunk kc resident in stage st
    __syncthreads();       // + all warps done with the stage we will overwrite
    if (kc + STAGES - 1 < NCHUNK) load_chunk(kc + STAGES - 1, (kc + STAGES - 1) % STAGES);
    cp_commit();

    const uint32_t sa = abase + st * A_STAGE;
    const uint32_t sb = bbase + st * B_STAGE;

    #pragma unroll
    for (int ks = 0; ks < BK / 32; ks++) {               // 4 k-steps of 32
      uint32_t af[4][4];
      #pragma unroll
      for (int mt = 0; mt < 4; mt++)
        ldm4(af[mt], sa + swz(((a_row_l + mt * 16) << 7) + a_byt_l + ks * 32));
      uint32_t bf[2][4];
      #pragma unroll
      for (int np = 0; np < 2; np++)
        ldm4(bf[np], sb + swz(((b_row_l + np * 16) << 7) + b_byt_l + ks * 32));
      #pragma unroll
      for (int mt = 0; mt < 4; mt++)
        #pragma unroll
        for (int nt = 0; nt < 4; nt++)
          mma_s8(acc[mt][nt], af[mt], &bf[nt >> 1][(nt & 1) * 2]);
    }
  }

  // ---- epilogue: scale, round(half-even), clamp -> float32 direct to gmem ----
  {
    const int qr = lane >> 2, qc = lane & 3;
    #pragma unroll
    for (int mt = 0; mt < 4; mt++) {
      const int r0 = warp_m * 64 + mt * 16 + qr;
      const int r1 = r0 + 8;
      const float rxy0 = __fdiv_rn(sxp[m0 + r0], syp[m0 + r0]);
      const float rxy1 = __fdiv_rn(sxp[m0 + r1], syp[m0 + r1]);
      float* o0 = out + (size_t)(m0 + r0) * ND + n0;
      float* o1 = out + (size_t)(m0 + r1) * ND + n0;
      #pragma unroll
      for (int nt = 0; nt < 4; nt++) {
        const int c0 = warp_n * 32 + nt * 8 + 2 * qc;
        const float sw0 = swp[n0 + c0], sw1 = swp[n0 + c0 + 1];
        const int* d = acc[mt][nt];

        const float s00 = __fmul_rn(rxy0, sw0), s01 = __fmul_rn(rxy0, sw1);
        const float s10 = __fmul_rn(rxy1, sw0), s11 = __fmul_rn(rxy1, sw1);
        int q00 = __float2int_rn(__fmul_rn(__int2float_rn(d[0]), s00));
        int q01 = __float2int_rn(__fmul_rn(__int2float_rn(d[1]), s01));
        int q10 = __float2int_rn(__fmul_rn(__int2float_rn(d[2]), s10));
        int q11 = __float2int_rn(__fmul_rn(__int2float_rn(d[3]), s11));
        q00 = q00 < -128 ? -128 : (q00 > 127 ? 127 : q00);
        q01 = q01 < -128 ? -128 : (q01 > 127 ? 127 : q01);
        q10 = q10 < -128 ? -128 : (q10 > 127 ? 127 : q10);
        q11 = q11 < -128 ? -128 : (q11 > 127 ? 127 : q11);

        *(float2*)(o0 + c0) = make_float2((float)q00, (float)q01);
        *(float2*)(o1 + c0) = make_float2((float)q10, (float)q11);
      }
    }
  }
}

} // namespace i8g

extern "C" void kernel_launch(void* const* d_in, const int* in_sizes, int n_in,
                              void* d_out, int out_size) {
  using namespace i8g;

  // Bind inputs by element count (counts are promotion-invariant).
  const void* x = nullptr; const void* w = nullptr;
  const float *sx = nullptr, *sw = nullptr, *sy = nullptr;
  for (int i = 0; i < n_in; i++) {
    const long long n = (long long)in_sizes[i];
    if (n == (long long)SD * KD)       x = d_in[i];
    else if (n == (long long)ND * KD)  w = d_in[i];
    else if (n == ND)                  sw = (const float*)d_in[i];
    else if (n == SD) { if (!sx) sx = (const float*)d_in[i]; else sy = (const float*)d_in[i]; }
  }
  if (!x || !w || !sx || !sw || !sy) return;

  float* out = (float*)d_out;

  // 1) decode promoted int8 inputs (int32- or float32-stored) into int8 scratch
  {
    const int nx16 = (SD * KD) / 16;   // 2097152
    const int nw16 = (ND * KD) / 16;   // 1048576
    pack_kernel<<<nx16 / 256, 256>>>((const uint4*)x, 0, nx16);
    pack_kernel<<<nw16 / 256, 256>>>((const uint4*)w, 1, nw16);
  }

  // 2) tensor-core int8 GEMM + fused dequant/requant epilogue
  cudaFuncSetAttribute(i8gemm_kernel, cudaFuncAttributeMaxDynamicSharedMemorySize,
                       (int)SMEM_BYTES);
  dim3 grid(ND / BN, SD / BM);   // (32, 64)
  i8gemm_kernel<<<grid, THREADS, SMEM_BYTES>>>(sx, sw, sy, out);

  // 3) scale_y passthrough: outputs packed [out_q (S*N floats)][scale_y (S floats)]
  const size_t SN = (size_t)SD * (size_t)ND;
  if ((size_t)out_size > SN) {
    cudaMemcpyAsync((float*)d_out + SN, sy,
                    ((size_t)out_size - SN) * sizeof(float),
                    cudaMemcpyDeviceToDevice);
  }
}

// round 8
// speedup vs baseline: 1.0539x; 1.0539x over previous
#include <cuda_runtime.h>
#include <cstdint>

#define DINL __device__ __forceinline__

namespace i8g {

constexpr int SD = 8192, KD = 4096, ND = 4096;
constexpr int BM = 128, BN = 128, BK = 128;     // CTA tile; BK in int8 elements
constexpr int STAGES = 3;
constexpr int NCHUNK = KD / BK;                 // 32
constexpr int THREADS = 256;                    // 8 warps: 2 (M) x 4 (N)

constexpr int A_STAGE = BM * BK;                // 16 KB
constexpr int B_STAGE = BN * BK;                // 16 KB
constexpr uint32_t OFF_A = 0;
constexpr uint32_t OFF_B = STAGES * A_STAGE;    // 48 KB
constexpr uint32_t SMEM_BYTES = OFF_B + STAGES * B_STAGE + 1024;  // ~97 KB

// int8 scratch for decoded inputs (promotion-corrected)
__device__ __align__(16) int8_t g_xq[(size_t)SD * KD];   // 32 MB
__device__ __align__(16) int8_t g_wq[(size_t)ND * KD];   // 16 MB

DINL uint32_t smem_u32(const void* p) {
  uint32_t a;
  asm("{ .reg .u64 t; cvta.to.shared.u64 t, %1; cvt.u32.u64 %0, t; }" : "=r"(a) : "l"(p));
  return a;
}
DINL uint32_t swz(uint32_t o) { return o ^ ((o >> 3) & 0x70); }   // SW128
DINL void cp16(uint32_t d, const void* s) {
  asm volatile("cp.async.cg.shared.global [%0], [%1], 16;" :: "r"(d), "l"(s) : "memory");
}
DINL void cp_commit() { asm volatile("cp.async.commit_group;" ::: "memory"); }
DINL void cp_wait1()  { asm volatile("cp.async.wait_group 1;" ::: "memory"); }

// NOTE: no "memory" clobber — producer/consumer ordering is enforced by
// cp.async.wait_group + __syncthreads; letting ptxas batch LDSMs is the point.
DINL void ldm4(uint32_t* r, uint32_t addr) {
  asm volatile("ldmatrix.sync.aligned.m8n8.x4.shared.b16 {%0,%1,%2,%3}, [%4];"
               : "=r"(r[0]), "=r"(r[1]), "=r"(r[2]), "=r"(r[3]) : "r"(addr));
}
DINL void mma_s8(int* d, const uint32_t* a, const uint32_t* b) {
  asm volatile(
      "mma.sync.aligned.m16n8k32.row.col.s32.s8.s8.s32 "
      "{%0,%1,%2,%3}, {%4,%5,%6,%7}, {%8,%9}, {%0,%1,%2,%3};"
      : "+r"(d[0]), "+r"(d[1]), "+r"(d[2]), "+r"(d[3])
      : "r"(a[0]), "r"(a[1]), "r"(a[2]), "r"(a[3]), "r"(b[0]), "r"(b[1]));
}

// ---- input decode: word is either int32 in [-128,127] or float32 of a small int ----
DINL int cvt_word(uint32_t u) {
  const int iv = (int)u;
  if (iv >= -128 && iv <= 127) return iv;          // int32-promoted input
  return __float2int_rn(__uint_as_float(u));       // float32-promoted input
}
DINL uint32_t pack4(uint4 v) {
  const int a = cvt_word(v.x), b = cvt_word(v.y), c = cvt_word(v.z), d = cvt_word(v.w);
  return (uint32_t)(a & 0xff) | ((uint32_t)(b & 0xff) << 8) |
         ((uint32_t)(c & 0xff) << 16) | ((uint32_t)(d & 0xff) << 24);
}

constexpr int NX16 = (SD * KD) / 16;   // 2097152 x-chunks of 16 elems
constexpr int NW16 = (ND * KD) / 16;   // 1048576 w-chunks

__global__ void __launch_bounds__(256)
pack_all_kernel(const uint4* __restrict__ xsrc, const uint4* __restrict__ wsrc)
{
  const int idx = blockIdx.x * blockDim.x + threadIdx.x;
  const uint4* s;
  uint4* dst;
  int o;
  if (idx < NX16) { s = xsrc + (size_t)idx * 4; dst = (uint4*)g_xq; o = idx; }
  else if (idx < NX16 + NW16) { s = wsrc + (size_t)(idx - NX16) * 4; dst = (uint4*)g_wq; o = idx - NX16; }
  else return;
  uint4 v;
  v.x = pack4(s[0]); v.y = pack4(s[1]); v.z = pack4(s[2]); v.w = pack4(s[3]);
  dst[o] = v;
}

__global__ void __launch_bounds__(THREADS, 2)
i8gemm_kernel(const float* __restrict__ sxp, const float* __restrict__ swp,
              const float* __restrict__ syp, float* __restrict__ out)
{
  extern __shared__ char smraw[];
  const uint32_t sraw = smem_u32(smraw);
  const uint32_t base = (sraw + 1023u) & ~1023u;   // 1024-align for SW128 math

  const int tid    = threadIdx.x;
  const int wid    = tid >> 5;
  const int lane   = tid & 31;
  const int warp_m = wid & 1;       // 0..1 -> 64-row slab
  const int warp_n = wid >> 1;      // 0..3 -> 32-col slab
  const int m0 = blockIdx.y * BM;
  const int n0 = blockIdx.x * BN;

  const uint32_t abase = base + OFF_A;
  const uint32_t bbase = base + OFF_B;
  const int8_t* __restrict__ x = g_xq;
  const int8_t* __restrict__ w = g_wq;

  // ---- producer: one 128B K-chunk of A[128 rows] + B[128 rows], SW128 swizzled ----
  auto load_chunk = [&](int kc, int st) {
    const int8_t* ga = x + (size_t)m0 * KD + (size_t)kc * BK;
    const uint32_t sa = abase + st * A_STAGE;
    #pragma unroll
    for (int i = 0; i < (BM * BK / 16) / THREADS; i++) {   // 4
      int u = i * THREADS + tid;
      int r = u >> 3, c = (u & 7) << 4;
      cp16(sa + swz((uint32_t)((r << 7) + c)), ga + (size_t)r * KD + c);
    }
    const int8_t* gb = w + (size_t)n0 * KD + (size_t)kc * BK;
    const uint32_t sb = bbase + st * B_STAGE;
    #pragma unroll
    for (int i = 0; i < (BN * BK / 16) / THREADS; i++) {   // 4
      int u = i * THREADS + tid;
      int r = u >> 3, c = (u & 7) << 4;
      cp16(sb + swz((uint32_t)((r << 7) + c)), gb + (size_t)r * KD + c);
    }
  };

  // ---- prologue ----
  #pragma unroll
  for (int s = 0; s < STAGES - 1; s++) { load_chunk(s, s); cp_commit(); }

  // ---- accumulators: warp tile 64x32 => 4x4 m16n8 tiles ----
  int acc[4][4][4];
  #pragma unroll
  for (int i = 0; i < 4; i++)
    #pragma unroll
    for (int j = 0; j < 4; j++)
      #pragma unroll
      for (int k = 0; k < 4; k++) acc[i][j][k] = 0;

  // ldmatrix per-lane address components
  const uint32_t a_row_l = (uint32_t)(warp_m * 64 + (lane & 15));
  const uint32_t a_byt_l = (uint32_t)((lane >> 4) << 4);
  const uint32_t b_row_l = (uint32_t)(warp_n * 32 + (lane & 7) + ((lane & 16) ? 8 : 0));
  const uint32_t b_byt_l = (uint32_t)((lane & 8) ? 16 : 0);

  // ---- mainloop ----
  for (int kc = 0; kc < NCHUNK; kc++) {
    const int st = kc % STAGES;
    cp_wait1();            // chunk kc resident in stage st
    __syncthreads();       // + all warps done with the stage we will overwrite
    if (kc + STAGES - 1 < NCHUNK) load_chunk(kc + STAGES - 1, (kc + STAGES - 1) % STAGES);
    cp_commit();

    const uint32_t sa = abase + st * A_STAGE;
    const uint32_t sb = bbase + st * B_STAGE;

    #pragma unroll
    for (int ks = 0; ks < BK / 32; ks++) {               // 4 k-steps of 32
      uint32_t af[4][4];
      #pragma unroll
      for (int mt = 0; mt < 4; mt++)
        ldm4(af[mt], sa + swz(((a_row_l + mt * 16) << 7) + a_byt_l + ks * 32));
      uint32_t bf[2][4];
      #pragma unroll
      for (int np = 0; np < 2; np++)
        ldm4(bf[np], sb + swz(((b_row_l + np * 16) << 7) + b_byt_l + ks * 32));
      #pragma unroll
      for (int mt = 0; mt < 4; mt++)
        #pragma unroll
        for (int nt = 0; nt < 4; nt++)
          mma_s8(acc[mt][nt], af[mt], &bf[nt >> 1][(nt & 1) * 2]);
    }
  }

  // ---- epilogue: scale, round(half-even), clamp -> float32 direct to gmem ----
  {
    const int qr = lane >> 2, qc = lane & 3;
    #pragma unroll
    for (int mt = 0; mt < 4; mt++) {
      const int r0 = warp_m * 64 + mt * 16 + qr;
      const int r1 = r0 + 8;
      const float rxy0 = __fdiv_rn(sxp[m0 + r0], syp[m0 + r0]);
      const float rxy1 = __fdiv_rn(sxp[m0 + r1], syp[m0 + r1]);
      float* o0 = out + (size_t)(m0 + r0) * ND + n0;
      float* o1 = out + (size_t)(m0 + r1) * ND + n0;
      #pragma unroll
      for (int nt = 0; nt < 4; nt++) {
        const int c0 = warp_n * 32 + nt * 8 + 2 * qc;
        const float sw0 = swp[n0 + c0], sw1 = swp[n0 + c0 + 1];
        const int* d = acc[mt][nt];

        const float s00 = __fmul_rn(rxy0, sw0), s01 = __fmul_rn(rxy0, sw1);
        const float s10 = __fmul_rn(rxy1, sw0), s11 = __fmul_rn(rxy1, sw1);
        int q00 = __float2int_rn(__fmul_rn(__int2float_rn(d[0]), s00));
        int q01 = __float2int_rn(__fmul_rn(__int2float_rn(d[1]), s01));
        int q10 = __float2int_rn(__fmul_rn(__int2float_rn(d[2]), s10));
        int q11 = __float2int_rn(__fmul_rn(__int2float_rn(d[3]), s11));
        q00 = q00 < -128 ? -128 : (q00 > 127 ? 127 : q00);
        q01 = q01 < -128 ? -128 : (q01 > 127 ? 127 : q01);
        q10 = q10 < -128 ? -128 : (q10 > 127 ? 127 : q10);
        q11 = q11 < -128 ? -128 : (q11 > 127 ? 127 : q11);

        *(float2*)(o0 + c0) = make_float2((float)q00, (float)q01);
        *(float2*)(o1 + c0) = make_float2((float)q10, (float)q11);
      }
    }
  }
}

} // namespace i8g

extern "C" void kernel_launch(void* const* d_in, const int* in_sizes, int n_in,
                              void* d_out, int out_size) {
  using namespace i8g;

  // Bind inputs by element count (counts are promotion-invariant).
  const void* x = nullptr; const void* w = nullptr;
  const float *sx = nullptr, *sw = nullptr, *sy = nullptr;
  for (int i = 0; i < n_in; i++) {
    const long long n = (long long)in_sizes[i];
    if (n == (long long)SD * KD)       x = d_in[i];
    else if (n == (long long)ND * KD)  w = d_in[i];
    else if (n == ND)                  sw = (const float*)d_in[i];
    else if (n == SD) { if (!sx) sx = (const float*)d_in[i]; else sy = (const float*)d_in[i]; }
  }
  if (!x || !w || !sx || !sw || !sy) return;

  float* out = (float*)d_out;

  // 1) decode promoted int8 inputs into int8 scratch (single fused launch)
  {
    const int total = NX16 + NW16;                 // 3145728
    pack_all_kernel<<<(total + 255) / 256, 256>>>((const uint4*)x, (const uint4*)w);
  }

  // 2) tensor-core int8 GEMM + fused dequant/requant epilogue
  cudaFuncSetAttribute(i8gemm_kernel, cudaFuncAttributeMaxDynamicSharedMemorySize,
                       (int)SMEM_BYTES);
  dim3 grid(ND / BN, SD / BM);   // (32, 64)
  i8gemm_kernel<<<grid, THREADS, SMEM_BYTES>>>(sx, sw, sy, out);

  // 3) scale_y passthrough: outputs packed [out_q (S*N floats)][scale_y (S floats)]
  const size_t SN = (size_t)SD * (size_t)ND;
  if ((size_t)out_size > SN) {
    cudaMemcpyAsync((float*)d_out + SN, sy,
                    ((size_t)out_size - SN) * sizeof(float),
                    cudaMemcpyDeviceToDevice);
  }
}

// round 9
// speedup vs baseline: 1.6388x; 1.5550x over previous
#include <cuda_runtime.h>
#include <cstdint>

#define DINL __device__ __forceinline__

namespace i8g {

constexpr int SD = 8192, KD = 4096, ND = 4096;
constexpr int BM = 128, BN = 128, BK = 128;     // CTA tile; BK in int8 elements
constexpr int STAGES = 3;
constexpr int NCHUNK = KD / BK;                 // 32
constexpr int THREADS = 256;                    // 8 warps: 4 IMMA + 4 dp4a

constexpr int A_STAGE = BM * BK;                // 16 KB
constexpr int B_STAGE = BN * BK;                // 16 KB
constexpr uint32_t OFF_A = 0;
constexpr uint32_t OFF_B = STAGES * A_STAGE;    // 48 KB
constexpr uint32_t SMEM_BYTES = OFF_B + STAGES * B_STAGE + 1024;  // ~97 KB

// int8 scratch for decoded inputs (promotion-corrected)
__device__ __align__(16) int8_t g_xq[(size_t)SD * KD];   // 32 MB
__device__ __align__(16) int8_t g_wq[(size_t)ND * KD];   // 16 MB

DINL uint32_t smem_u32(const void* p) {
  uint32_t a;
  asm("{ .reg .u64 t; cvta.to.shared.u64 t, %1; cvt.u32.u64 %0, t; }" : "=r"(a) : "l"(p));
  return a;
}
DINL uint32_t swz(uint32_t o) { return o ^ ((o >> 3) & 0x70); }   // SW128
DINL void cp16(uint32_t d, const void* s) {
  asm volatile("cp.async.cg.shared.global [%0], [%1], 16;" :: "r"(d), "l"(s) : "memory");
}
DINL void cp_commit() { asm volatile("cp.async.commit_group;" ::: "memory"); }
DINL void cp_wait1()  { asm volatile("cp.async.wait_group 1;" ::: "memory"); }

DINL void ldm4(uint32_t* r, uint32_t addr) {
  asm volatile("ldmatrix.sync.aligned.m8n8.x4.shared.b16 {%0,%1,%2,%3}, [%4];"
               : "=r"(r[0]), "=r"(r[1]), "=r"(r[2]), "=r"(r[3]) : "r"(addr));
}
DINL void mma_s8(int* d, const uint32_t* a, const uint32_t* b) {
  asm volatile(
      "mma.sync.aligned.m16n8k32.row.col.s32.s8.s8.s32 "
      "{%0,%1,%2,%3}, {%4,%5,%6,%7}, {%8,%9}, {%0,%1,%2,%3};"
      : "+r"(d[0]), "+r"(d[1]), "+r"(d[2]), "+r"(d[3])
      : "r"(a[0]), "r"(a[1]), "r"(a[2]), "r"(a[3]), "r"(b[0]), "r"(b[1]));
}
DINL int2 lds64(uint32_t addr) {
  int2 v;
  asm volatile("ld.shared.v2.b32 {%0,%1}, [%2];" : "=r"(v.x), "=r"(v.y) : "r"(addr));
  return v;
}

// ---- input decode: word is either int32 in [-128,127] or float32 of a small int ----
DINL int cvt_word(uint32_t u) {
  const int iv = (int)u;
  if (iv >= -128 && iv <= 127) return iv;
  return __float2int_rn(__uint_as_float(u));
}
DINL uint32_t pack4(uint4 v) {
  const int a = cvt_word(v.x), b = cvt_word(v.y), c = cvt_word(v.z), d = cvt_word(v.w);
  return (uint32_t)(a & 0xff) | ((uint32_t)(b & 0xff) << 8) |
         ((uint32_t)(c & 0xff) << 16) | ((uint32_t)(d & 0xff) << 24);
}

constexpr int NX16 = (SD * KD) / 16;
constexpr int NW16 = (ND * KD) / 16;

__global__ void __launch_bounds__(256)
pack_all_kernel(const uint4* __restrict__ xsrc, const uint4* __restrict__ wsrc)
{
  const int idx = blockIdx.x * blockDim.x + threadIdx.x;
  const uint4* s;
  uint4* dst;
  int o;
  if (idx < NX16) { s = xsrc + (size_t)idx * 4; dst = (uint4*)g_xq; o = idx; }
  else if (idx < NX16 + NW16) { s = wsrc + (size_t)(idx - NX16) * 4; dst = (uint4*)g_wq; o = idx - NX16; }
  else return;
  uint4 v;
  v.x = pack4(s[0]); v.y = pack4(s[1]); v.z = pack4(s[2]); v.w = pack4(s[3]);
  dst[o] = v;
}

__global__ void __launch_bounds__(THREADS, 2)
i8gemm_kernel(const float* __restrict__ sxp, const float* __restrict__ swp,
              const float* __restrict__ syp, float* __restrict__ out)
{
  extern __shared__ char smraw[];
  const uint32_t sraw = smem_u32(smraw);
  const uint32_t base = (sraw + 1023u) & ~1023u;

  const int tid  = threadIdx.x;
  const int wid  = tid >> 5;
  const int lane = tid & 31;
  const int m0 = blockIdx.y * BM;
  const int n0 = blockIdx.x * BN;

  const uint32_t abase = base + OFF_A;
  const uint32_t bbase = base + OFF_B;
  const int8_t* __restrict__ x = g_xq;
  const int8_t* __restrict__ w = g_wq;

  // ---- producer (all 256 threads): SW128-swizzled A[128] + B[128] rows ----
  auto load_chunk = [&](int kc, int st) {
    const int8_t* ga = x + (size_t)m0 * KD + (size_t)kc * BK;
    const uint32_t sa = abase + st * A_STAGE;
    #pragma unroll
    for (int i = 0; i < (BM * BK / 16) / THREADS; i++) {
      int u = i * THREADS + tid;
      int r = u >> 3, c = (u & 7) << 4;
      cp16(sa + swz((uint32_t)((r << 7) + c)), ga + (size_t)r * KD + c);
    }
    const int8_t* gb = w + (size_t)n0 * KD + (size_t)kc * BK;
    const uint32_t sb = bbase + st * B_STAGE;
    #pragma unroll
    for (int i = 0; i < (BN * BK / 16) / THREADS; i++) {
      int u = i * THREADS + tid;
      int r = u >> 3, c = (u & 7) << 4;
      cp16(sb + swz((uint32_t)((r << 7) + c)), gb + (size_t)r * KD + c);
    }
  };

  #pragma unroll
  for (int s = 0; s < STAGES - 1; s++) { load_chunk(s, s); cp_commit(); }

  if (wid < 4) {
    // ================= IMMA half: cols [0,64) — 2x2 warps of 64x32 =================
    const int warp_m = wid & 1;
    const int warp_n = (wid >> 1) & 1;

    int acc[4][4][4];
    #pragma unroll
    for (int i = 0; i < 4; i++)
      #pragma unroll
      for (int j = 0; j < 4; j++)
        #pragma unroll
        for (int k = 0; k < 4; k++) acc[i][j][k] = 0;

    const uint32_t a_row_l = (uint32_t)(warp_m * 64 + (lane & 15));
    const uint32_t a_byt_l = (uint32_t)((lane >> 4) << 4);
    const uint32_t b_row_l = (uint32_t)(warp_n * 32 + (lane & 7) + ((lane & 16) ? 8 : 0));
    const uint32_t b_byt_l = (uint32_t)((lane & 8) ? 16 : 0);

    for (int kc = 0; kc < NCHUNK; kc++) {
      const int st = kc % STAGES;
      cp_wait1();
      __syncthreads();
      if (kc + STAGES - 1 < NCHUNK) load_chunk(kc + STAGES - 1, (kc + STAGES - 1) % STAGES);
      cp_commit();

      const uint32_t sa = abase + st * A_STAGE;
      const uint32_t sb = bbase + st * B_STAGE;

      #pragma unroll
      for (int ks = 0; ks < BK / 32; ks++) {
        uint32_t af[4][4];
        #pragma unroll
        for (int mt = 0; mt < 4; mt++)
          ldm4(af[mt], sa + swz(((a_row_l + mt * 16) << 7) + a_byt_l + ks * 32));
        uint32_t bf[2][4];
        #pragma unroll
        for (int np = 0; np < 2; np++)
          ldm4(bf[np], sb + swz(((b_row_l + np * 16) << 7) + b_byt_l + ks * 32));
        #pragma unroll
        for (int mt = 0; mt < 4; mt++)
          #pragma unroll
          for (int nt = 0; nt < 4; nt++)
            mma_s8(acc[mt][nt], af[mt], &bf[nt >> 1][(nt & 1) * 2]);
      }
    }

    // epilogue (cols 0..63)
    const int qr = lane >> 2, qc = lane & 3;
    #pragma unroll
    for (int mt = 0; mt < 4; mt++) {
      const int r0 = warp_m * 64 + mt * 16 + qr;
      const int r1 = r0 + 8;
      const float rxy0 = __fdiv_rn(sxp[m0 + r0], syp[m0 + r0]);
      const float rxy1 = __fdiv_rn(sxp[m0 + r1], syp[m0 + r1]);
      float* o0 = out + (size_t)(m0 + r0) * ND + n0;
      float* o1 = out + (size_t)(m0 + r1) * ND + n0;
      #pragma unroll
      for (int nt = 0; nt < 4; nt++) {
        const int c0 = warp_n * 32 + nt * 8 + 2 * qc;
        const float sw0 = swp[n0 + c0], sw1 = swp[n0 + c0 + 1];
        const int* d = acc[mt][nt];
        const float s00 = __fmul_rn(rxy0, sw0), s01 = __fmul_rn(rxy0, sw1);
        const float s10 = __fmul_rn(rxy1, sw0), s11 = __fmul_rn(rxy1, sw1);
        int q00 = __float2int_rn(__fmul_rn(__int2float_rn(d[0]), s00));
        int q01 = __float2int_rn(__fmul_rn(__int2float_rn(d[1]), s01));
        int q10 = __float2int_rn(__fmul_rn(__int2float_rn(d[2]), s10));
        int q11 = __float2int_rn(__fmul_rn(__int2float_rn(d[3]), s11));
        q00 = q00 < -128 ? -128 : (q00 > 127 ? 127 : q00);
        q01 = q01 < -128 ? -128 : (q01 > 127 ? 127 : q01);
        q10 = q10 < -128 ? -128 : (q10 > 127 ? 127 : q10);
        q11 = q11 < -128 ? -128 : (q11 > 127 ? 127 : q11);
        *(float2*)(o0 + c0) = make_float2((float)q00, (float)q01);
        *(float2*)(o1 + c0) = make_float2((float)q10, (float)q11);
      }
    }
  } else {
    // ================= dp4a half: cols [64,128) — 4 warps, 8x8 blocking =============
    const int dw = wid - 4;              // 0..3
    const int tx = lane & 7;             // col group: cols 64 + tx + 8j
    const int ry = lane >> 3;            // 0..3
    const int rowbase = dw * 4 + ry;     // 0..15; rows rowbase + 16i
    // Conflict-free under SW128: (row&7)=rowbase&7 distinct per ry within warp;
    // (wrow&7)=tx distinct per tx. XOR masks constant per thread:
    const uint32_t xra = (uint32_t)(rowbase & 7) << 4;
    const uint32_t xrb = (uint32_t)(tx & 7) << 4;
    const uint32_t aoff = (uint32_t)rowbase << 7;           // + i*2048
    const uint32_t boff = (uint32_t)(64 + tx) << 7;         // + j*1024

    int dacc[8][8];
    #pragma unroll
    for (int i = 0; i < 8; i++)
      #pragma unroll
      for (int j = 0; j < 8; j++) dacc[i][j] = 0;

    for (int kc = 0; kc < NCHUNK; kc++) {
      const int st = kc % STAGES;
      cp_wait1();
      __syncthreads();
      if (kc + STAGES - 1 < NCHUNK) load_chunk(kc + STAGES - 1, (kc + STAGES - 1) % STAGES);
      cp_commit();

      const uint32_t sa = abase + st * A_STAGE;
      const uint32_t sb = bbase + st * B_STAGE;

      #pragma unroll 2
      for (int kk2 = 0; kk2 < BK / 8; kk2++) {              // 2 k-words per iter
        const uint32_t ka = sa + aoff + (((uint32_t)kk2 << 3) ^ xra);
        const uint32_t kb = sb + boff + (((uint32_t)kk2 << 3) ^ xrb);
        int2 a2[8], b2[8];
        #pragma unroll
        for (int i = 0; i < 8; i++) a2[i] = lds64(ka + i * 2048);
        #pragma unroll
        for (int j = 0; j < 8; j++) b2[j] = lds64(kb + j * 1024);
        #pragma unroll
        for (int i = 0; i < 8; i++)
          #pragma unroll
          for (int j = 0; j < 8; j++) {
            dacc[i][j] = __dp4a(a2[i].x, b2[j].x, dacc[i][j]);
            dacc[i][j] = __dp4a(a2[i].y, b2[j].y, dacc[i][j]);
          }
      }
    }

    // epilogue (cols 64..127)
    #pragma unroll
    for (int i = 0; i < 8; i++) {
      const int r = m0 + rowbase + 16 * i;
      const float rxy = __fdiv_rn(sxp[r], syp[r]);
      float* o = out + (size_t)r * ND;
      #pragma unroll
      for (int j = 0; j < 8; j++) {
        const int c = n0 + 64 + tx + 8 * j;
        const float s = __fmul_rn(rxy, swp[c]);
        const float f = __fmul_rn(__int2float_rn(dacc[i][j]), s);
        int q = __float2int_rn(f);
        q = q < -128 ? -128 : (q > 127 ? 127 : q);
        o[c] = (float)q;
      }
    }
  }
}

} // namespace i8g

extern "C" void kernel_launch(void* const* d_in, const int* in_sizes, int n_in,
                              void* d_out, int out_size) {
  using namespace i8g;

  const void* x = nullptr; const void* w = nullptr;
  const float *sx = nullptr, *sw = nullptr, *sy = nullptr;
  for (int i = 0; i < n_in; i++) {
    const long long n = (long long)in_sizes[i];
    if (n == (long long)SD * KD)       x = d_in[i];
    else if (n == (long long)ND * KD)  w = d_in[i];
    else if (n == ND)                  sw = (const float*)d_in[i];
    else if (n == SD) { if (!sx) sx = (const float*)d_in[i]; else sy = (const float*)d_in[i]; }
  }
  if (!x || !w || !sx || !sw || !sy) return;

  float* out = (float*)d_out;

  {
    const int total = NX16 + NW16;
    pack_all_kernel<<<(total + 255) / 256, 256>>>((const uint4*)x, (const uint4*)w);
  }

  cudaFuncSetAttribute(i8gemm_kernel, cudaFuncAttributeMaxDynamicSharedMemorySize,
                       (int)SMEM_BYTES);
  dim3 grid(ND / BN, SD / BM);   // (32, 64)
  i8gemm_kernel<<<grid, THREADS, SMEM_BYTES>>>(sx, sw, sy, out);

  const size_t SN = (size_t)SD * (size_t)ND;
  if ((size_t)out_size > SN) {
    cudaMemcpyAsync((float*)d_out + SN, sy,
                    ((size_t)out_size - SN) * sizeof(float),
                    cudaMemcpyDeviceToDevice);
  }
}